// round 16
// baseline (speedup 1.0000x reference)
#include <cuda_runtime.h>
#include <cstdint>
#include <math.h>

#define B_   64
#define S_   512
#define I_   256
#define H_   512
#define G4H  2048
#define GRID 128
#define NTH  512
#define HCW  132          // h chunk row width (128 + 4 pad)
#define CHB  (64*HCW*4)   // h chunk bytes (33792)

typedef unsigned long long ull;

// SMEM float counts (recurrent kernel)
#define F_U   (512*16)        // U weights, layout [k*16 + gate*4 + jl]
#define F_H   (4*64*HCW)      // 4 chunks x [64][132]
#define F_XP  (4*64*16)       // 4-slot xp ring [64][16]
#define F_P   (128*20)        // partials [kh*64+b][20]
#define F_HO  (64*4)          // staged h output
#define SMEM_FLOATS (F_U + F_H + F_XP + F_P + F_HO)
#define SMEM_BYTES  (SMEM_FLOATS*4 + 128)

// ---------------- static device scratch ----------------
__device__ __align__(256) float g_xp[(size_t)S_ * GRID * B_ * 16]; // [t][blk][b][16]
__device__ __align__(256) float g_h[2 * 4 * B_ * HCW];             // [par][chunk][b][132]
__device__ unsigned g_prod[2][4];   // producers-done counters (monotonic)
__device__ unsigned g_cons[2];      // consumers-done counters (monotonic)

// ---------------- PTX helpers ----------------
__device__ __forceinline__ unsigned sm2u(const void* p) {
    unsigned a;
    asm("{ .reg .u64 t; cvta.to.shared.u64 t, %1; cvt.u32.u64 %0, t; }" : "=r"(a) : "l"(p));
    return a;
}
__device__ __forceinline__ void mbar_init(unsigned a, unsigned c) {
    asm volatile("mbarrier.init.shared.b64 [%0], %1;" :: "r"(a), "r"(c) : "memory");
}
__device__ __forceinline__ void mbar_arrive_expect(unsigned a, unsigned bytes) {
    asm volatile("mbarrier.arrive.expect_tx.shared.b64 _, [%0], %1;"
                 :: "r"(a), "r"(bytes) : "memory");
}
__device__ __forceinline__ void bulk_g2s(unsigned dst, const void* src,
                                         unsigned bytes, unsigned mbar) {
    asm volatile("cp.async.bulk.shared::cluster.global.mbarrier::complete_tx::bytes "
                 "[%0], [%1], %2, [%3];"
                 :: "r"(dst), "l"(src), "r"(bytes), "r"(mbar) : "memory");
}
__device__ __forceinline__ void mbar_wait(unsigned a, unsigned ph) {
    unsigned done = 0;
    while (!done) {
        asm volatile("{ .reg .pred p; "
                     "mbarrier.try_wait.parity.acquire.cta.shared::cta.b64 p, [%1], %2, 0x989680; "
                     "selp.b32 %0, 1, 0, p; }"
                     : "=r"(done) : "r"(a), "r"(ph) : "memory");
    }
}
__device__ __forceinline__ void poll_ge(const unsigned* p, unsigned target) {
    unsigned v;
    do {
        asm volatile("ld.acquire.gpu.global.u32 %0, [%1];" : "=r"(v) : "l"(p) : "memory");
    } while (v < target);
}
__device__ __forceinline__ void red_add(unsigned* p, unsigned v) {
    asm volatile("red.release.gpu.global.add.u32 [%0], %1;" :: "l"(p), "r"(v) : "memory");
}
__device__ __forceinline__ void fma2(ull& acc, ull a, ull b) {
    asm("fma.rn.f32x2 %0, %1, %2, %0;" : "+l"(acc) : "l"(a), "l"(b));
}
__device__ __forceinline__ ull dupf(float v) {
    ull r; asm("mov.b64 %0, {%1, %1};" : "=l"(r) : "f"(v)); return r;
}
__device__ __forceinline__ float rcp_(float x) {
    float y; asm("rcp.approx.f32 %0, %1;" : "=f"(y) : "f"(x)); return y;
}
__device__ __forceinline__ float sig_(float x)  { return rcp_(1.0f + __expf(-x)); }
__device__ __forceinline__ float tanh_(float x) { return fmaf(2.0f, rcp_(1.0f + __expf(-2.0f * x)), -1.0f); }

// 4 k-steps, 4 cols; conflict-free (weights: one 64B broadcast line per k)
__device__ __forceinline__ void dot4(const float* __restrict__ ab,
                                     const float* __restrict__ wu,
                                     ull& a01, ull& a23) {
    float4 h4 = *reinterpret_cast<const float4*>(ab);
#pragma unroll
    for (int j = 0; j < 4; ++j) {
        ull h = dupf((&h4.x)[j]);
        ulonglong2 w = *reinterpret_cast<const ulonglong2*>(wu + j * 16);
        fma2(a01, h, w.x);
        fma2(a23, h, w.y);
    }
}

// ---------------- init: zero h buffers + counters ----------------
__global__ void k_init() {
    int i = blockIdx.x * blockDim.x + threadIdx.x;
    if (i < 2 * 4 * B_ * HCW) g_h[i] = 0.0f;
    if (i < 8)  ((unsigned*)g_prod)[i] = 0u;
    if (i < 2)  g_cons[i] = 0u;
}

// ---------------- x-projection GEMM (f32x2): g_xp = x @ W + bias ----------------
__global__ void __launch_bounds__(256, 2)
k_xproj(const float* __restrict__ x, const float* __restrict__ W,
        const float* __restrict__ bias) {
    __shared__ float As[16][132];
    __shared__ float Bs[16][128];
    const int tid = threadIdx.x;
    const int tx = tid & 15, ty = tid >> 4;
    const int m0 = blockIdx.x * 128;
    const int n0 = blockIdx.y * 128;

    ull acc2[8][4];
#pragma unroll
    for (int r = 0; r < 8; ++r)
#pragma unroll
        for (int c = 0; c < 4; ++c) acc2[r][c] = 0ull;

    for (int k0 = 0; k0 < I_; k0 += 16) {
        __syncthreads();
#pragma unroll
        for (int i = tid; i < 512; i += 256) {
            int r = i >> 2, g = i & 3;
            float4 v = *reinterpret_cast<const float4*>(
                x + (size_t)(m0 + r) * I_ + k0 + g * 4);
            As[g * 4 + 0][r] = v.x; As[g * 4 + 1][r] = v.y;
            As[g * 4 + 2][r] = v.z; As[g * 4 + 3][r] = v.w;
        }
#pragma unroll
        for (int i = tid; i < 512; i += 256) {
            int kk = i >> 5, g = i & 31;
            *reinterpret_cast<float4*>(&Bs[kk][g * 4]) =
                *reinterpret_cast<const float4*>(W + (size_t)(k0 + kk) * G4H + n0 + g * 4);
        }
        __syncthreads();
#pragma unroll
        for (int kk = 0; kk < 16; ++kk) {
            float a[8];
            *reinterpret_cast<float4*>(a)     = *reinterpret_cast<float4*>(&As[kk][ty * 8]);
            *reinterpret_cast<float4*>(a + 4) = *reinterpret_cast<float4*>(&As[kk][ty * 8 + 4]);
            ull bw[4];
            {
                ulonglong2 p0 = *reinterpret_cast<ulonglong2*>(&Bs[kk][tx * 4]);
                ulonglong2 p1 = *reinterpret_cast<ulonglong2*>(&Bs[kk][tx * 4 + 64]);
                bw[0] = p0.x; bw[1] = p0.y; bw[2] = p1.x; bw[3] = p1.y;
            }
#pragma unroll
            for (int r = 0; r < 8; ++r) {
                ull ha = dupf(a[r]);
#pragma unroll
                for (int c = 0; c < 4; ++c) fma2(acc2[r][c], ha, bw[c]);
            }
        }
    }

    const int b  = m0 >> 9;
    const int tb = (m0 & 511) + ty * 8;
    float4 bias0 = *reinterpret_cast<const float4*>(bias + n0 + tx * 4);
    float4 bias1 = *reinterpret_cast<const float4*>(bias + n0 + tx * 4 + 64);
#pragma unroll
    for (int r = 0; r < 8; ++r) {
        int t = tb + r;
#pragma unroll
        for (int grp = 0; grp < 2; ++grp) {
            int n  = n0 + tx * 4 + grp * 64;
            int q  = n >> 9;
            int cg = (n & 511) >> 2;
            float f0, f1, f2, f3;
            asm("mov.b64 {%0, %1}, %2;" : "=f"(f0), "=f"(f1) : "l"(acc2[r][grp * 2 + 0]));
            asm("mov.b64 {%0, %1}, %2;" : "=f"(f2), "=f"(f3) : "l"(acc2[r][grp * 2 + 1]));
            float4 v;
            v.x = f0 + (grp ? bias1.x : bias0.x);
            v.y = f1 + (grp ? bias1.y : bias0.y);
            v.z = f2 + (grp ? bias1.z : bias0.z);
            v.w = f3 + (grp ? bias1.w : bias0.w);
            *reinterpret_cast<float4*>(
                g_xp + (((size_t)t * GRID + cg) * B_ + b) * 16 + q * 4) = v;
        }
    }
}

// ---------------- persistent recurrent kernel (barrier-free handoff) ----------------
__global__ void __launch_bounds__(NTH, 1)
k_lstm(const float* __restrict__ U, float* __restrict__ out) {
    extern __shared__ float sm[];
    float* sU   = sm;                 // [512][16]
    float* sH   = sU + F_U;           // 4 x [64][132]
    float* sXP  = sH + F_H;           // 4 x [64][16]
    float* sP   = sXP + F_XP;         // [128][20]
    float* sHo  = sP + F_P;           // [64][4]
    unsigned long long* mb = reinterpret_cast<unsigned long long*>(sHo + F_HO);
    const unsigned mbH0  = sm2u(mb);        // +8*c
    const unsigned mbXP0 = sm2u(mb + 4);    // +8*s
    const unsigned sH_u  = sm2u(sH);
    const unsigned sXP_u = sm2u(sXP);

    const int tid = threadIdx.x;
    const int blk = blockIdx.x;
    const int kh  = tid >> 8;         // K half: chunks {0,1} or {2,3}
    const int r   = tid & 255;
    const int b   = r >> 2;
    const int cq  = r & 3;
    const int bu  = r >> 2;           // update mapping (tid < 256)
    const int jl  = r & 3;
    const int hcol = blk * 4 + jl;
    const int mychunk = blk >> 5;     // chunk this CTA produces
    float c_state = 0.0f;

    // poller chunk for this warp's lane0 (order matches compute order)
    const int wid = tid >> 5;
    int pollc = -1;
    if (wid == 0) pollc = blk & 1;
    else if (wid == 8) pollc = 2 + (blk & 1);
    else if (wid == 1) pollc = 1 - (blk & 1);
    else if (wid == 9) pollc = 3 - (blk & 1);

    // ---- prologue ----
    if (tid == 0) {
#pragma unroll
        for (int i = 0; i < 8; ++i) mbar_init(mbH0 + i * 8, 1);
        asm volatile("fence.proxy.async.shared::cta;" ::: "memory");
    }
    for (int i = tid; i < 512 * 4; i += NTH) {
        int k = i >> 2, q = i & 3;
        float4 w = *reinterpret_cast<const float4*>(
            U + (size_t)k * G4H + q * H_ + blk * 4);
        *reinterpret_cast<float4*>(sU + k * 16 + q * 4) = w;
    }
    __syncthreads();
    if (tid == 64) {   // prefetch xp slots t=0..3
#pragma unroll
        for (int s = 0; s < 4; ++s) {
            mbar_arrive_expect(mbXP0 + s * 8, 4096);
            bulk_g2s(sXP_u + (unsigned)(s * 4096),
                     g_xp + ((size_t)s * GRID + blk) * (B_ * 16), 4096, mbXP0 + s * 8);
        }
    }

    const int c_first  = kh * 2 + (blk & 1);
    const int c_second = kh * 2 + ((blk & 1) ^ 1);

    for (int t = 0; t < S_; ++t) {
        const unsigned p = (unsigned)((t + 1) & 1);      // buffer to read
        const unsigned N = ((unsigned)(t + 1)) >> 1;     // handoff epoch

        // ---- per-chunk TMA: poll producers (32, not 128), then issue ----
        if ((tid & 31) == 0 && pollc >= 0) {
            if (N) poll_ge(&g_prod[p][pollc], 32u * N);
            unsigned mbh = mbH0 + (unsigned)(pollc * 8);
            mbar_arrive_expect(mbh, CHB);
            bulk_g2s(sH_u + (unsigned)(pollc * CHB),
                     g_h + ((size_t)(p * 4 + (unsigned)pollc)) * (64 * HCW),
                     CHB, mbh);
        }

        // ---- accumulator init ----
        const int s = t & 3;
        ull a01, a23;
        if (kh == 0) {
            mbar_wait(mbXP0 + (unsigned)(s * 8), (unsigned)((t >> 2) & 1));
            float4 xin = *reinterpret_cast<const float4*>(
                sXP + s * (64 * 16) + b * 16 + cq * 4);
            asm("mov.b64 %0, {%1, %2};" : "=l"(a01) : "f"(xin.x), "f"(xin.y));
            asm("mov.b64 %0, {%1, %2};" : "=l"(a23) : "f"(xin.z), "f"(xin.w));
        } else {
            a01 = 0ull; a23 = 0ull;
        }

        // ---- this half's 2 k-chunks of 128 ----
#pragma unroll
        for (int cc = 0; cc < 2; ++cc) {
            const int c = cc ? c_second : c_first;
            mbar_wait(mbH0 + (unsigned)(c * 8), (unsigned)(t & 1));
            const float* hb = sH + c * (64 * HCW) + b * HCW;
            const float* wb = sU + (c * 128) * 16 + cq * 4;
#pragma unroll 4
            for (int kk = 0; kk < 128; kk += 4)
                dot4(hb + kk, wb + kk * 16, a01, a23);
        }

        // ---- write partials ----
        {
            float4 pv;
            asm("mov.b64 {%0, %1}, %2;" : "=f"(pv.x), "=f"(pv.y) : "l"(a01));
            asm("mov.b64 {%0, %1}, %2;" : "=f"(pv.z), "=f"(pv.w) : "l"(a23));
            *reinterpret_cast<float4*>(sP + (kh * 64 + b) * 20 + cq * 4) = pv;
        }
        __syncthreads();   // S1: all chunk TMAs consumed, partials ready

        if (tid == 96) red_add(&g_cons[p], 1u);          // our reads of buf p done
        if (tid == 64 && t + 4 < S_) {                   // xp refill (slot s consumed)
            mbar_arrive_expect(mbXP0 + (unsigned)(s * 8), 4096);
            bulk_g2s(sXP_u + (unsigned)(s * 4096),
                     g_xp + ((size_t)(t + 4) * GRID + blk) * (B_ * 16), 4096,
                     mbXP0 + (unsigned)(s * 8));
        }

        // ---- cell update (tid<256) | cons-poll (spare kh=1 warp) in parallel ----
        if (tid < 256) {
            const float* p0 = sP + bu * 20 + jl;
            const float* p1 = sP + (64 + bu) * 20 + jl;
            float gi = p0[0]  + p1[0];
            float gf = p0[4]  + p1[4];
            float gg = p0[8]  + p1[8];
            float go = p0[12] + p1[12];
            float iv = sig_(gi);
            float fv = sig_(gf);
            float gt = tanh_(gg);
            float ov = sig_(go);
            c_state = fv * c_state + iv * gt;
            float hv = ov * tanh_(c_state);
            sHo[bu * 4 + jl] = hv;
            if (t == S_ - 1) {
                size_t base = (size_t)B_ * S_ * H_;
                out[base + (size_t)bu * H_ + hcol] = hv;
                out[base + (size_t)B_ * H_ + (size_t)bu * H_ + hcol] = c_state;
            }
        } else if (tid == 320 && t) {
            // writer gate: all 128 CTAs finished reading buf[t&1] (step t-1 reads)
            poll_ge(&g_cons[t & 1], 128u * N);
        }
        __syncthreads();   // S2: sHo ready AND overwrite of buf[t&1] is safe

        // ---- coalesced h/out writes ----
        if (tid < 64) {
            float4 hv4 = *reinterpret_cast<float4*>(sHo + tid * 4);
            *reinterpret_cast<float4*>(
                out + ((size_t)tid * S_ + t) * H_ + blk * 4) = hv4;
            *reinterpret_cast<float4*>(
                g_h + ((size_t)((t & 1) * 4 + mychunk)) * (64 * HCW)
                    + (size_t)tid * HCW + (blk & 31) * 4) = hv4;
            __threadfence();
        }
        __syncthreads();   // S3: h writes globally ordered before prod arrive

        if (tid == 352) red_add(&g_prod[t & 1][mychunk], 1u);
    }
}

// ---------------- launch ----------------
extern "C" void kernel_launch(void* const* d_in, const int* in_sizes, int n_in,
                              void* d_out, int out_size) {
    const float* x = nullptr; const float* W = nullptr;
    const float* U = nullptr; const float* bias = nullptr;
    for (int i = 0; i < n_in; ++i) {
        switch (in_sizes[i]) {
            case B_ * S_ * I_: x    = (const float*)d_in[i]; break;
            case I_ * G4H:     W    = (const float*)d_in[i]; break;
            case H_ * G4H:     U    = (const float*)d_in[i]; break;
            case G4H:          bias = (const float*)d_in[i]; break;
            default: break;
        }
    }
    if (!x && n_in > 0)    x    = (const float*)d_in[0];
    if (!W && n_in > 1)    W    = (const float*)d_in[1];
    if (!U && n_in > 2)    U    = (const float*)d_in[2];
    if (!bias && n_in > 3) bias = (const float*)d_in[3];

    cudaFuncSetAttribute(k_lstm, cudaFuncAttributeMaxDynamicSharedMemorySize,
                         SMEM_BYTES);
    k_init<<<(2 * 4 * B_ * HCW + 255) / 256, 256>>>();
    k_xproj<<<dim3((B_ * S_) / 128, G4H / 128), 256>>>(x, W, bias);
    k_lstm<<<GRID, NTH, SMEM_BYTES>>>(U, (float*)d_out);
}

// round 17
// speedup vs baseline: 1.5397x; 1.5397x over previous
#include <cuda_runtime.h>
#include <cstdint>
#include <math.h>

#define B_   64
#define S_   512
#define I_   256
#define H_   512
#define G4H  2048
#define GRID 128
#define NTH  512
#define HCW  132          // h chunk row width (128 + 4 pad)
#define CHB  (64*HCW*4)   // h chunk bytes

typedef unsigned long long ull;

// SMEM float counts (recurrent kernel)
#define F_U   (512*16)        // U weights, layout [k*16 + gate*4 + jl]
#define F_H   (4*64*HCW)      // 4 chunks x [64][132]
#define F_XP  (4*64*16)       // 4-slot xp ring [64][16]
#define F_P   (4*64*20)       // partials [q*64+b][20]
#define F_HO  (64*4)          // staged h output
#define SMEM_FLOATS (F_U + F_H + F_XP + F_P + F_HO)
#define SMEM_BYTES  (SMEM_FLOATS*4 + 128)

// ---------------- static device scratch ----------------
__device__ __align__(256) float g_xp[(size_t)S_ * GRID * B_ * 16]; // [t][blk][b][16]
__device__ __align__(256) float g_h[4 * B_ * HCW];                 // [chunk][b][132]
__device__ unsigned g_cnt;                                         // monotonic barrier ctr

// ---------------- PTX helpers ----------------
__device__ __forceinline__ unsigned sm2u(const void* p) {
    unsigned a;
    asm("{ .reg .u64 t; cvta.to.shared.u64 t, %1; cvt.u32.u64 %0, t; }" : "=r"(a) : "l"(p));
    return a;
}
__device__ __forceinline__ void mbar_init(unsigned a, unsigned c) {
    asm volatile("mbarrier.init.shared.b64 [%0], %1;" :: "r"(a), "r"(c) : "memory");
}
__device__ __forceinline__ void mbar_arrive_expect(unsigned a, unsigned bytes) {
    asm volatile("mbarrier.arrive.expect_tx.shared.b64 _, [%0], %1;"
                 :: "r"(a), "r"(bytes) : "memory");
}
__device__ __forceinline__ void bulk_g2s(unsigned dst, const void* src,
                                         unsigned bytes, unsigned mbar) {
    asm volatile("cp.async.bulk.shared::cluster.global.mbarrier::complete_tx::bytes "
                 "[%0], [%1], %2, [%3];"
                 :: "r"(dst), "l"(src), "r"(bytes), "r"(mbar) : "memory");
}
__device__ __forceinline__ void mbar_wait(unsigned a, unsigned ph) {
    unsigned done = 0;
    while (!done) {
        asm volatile("{ .reg .pred p; "
                     "mbarrier.try_wait.parity.acquire.cta.shared::cta.b64 p, [%1], %2, 0x989680; "
                     "selp.b32 %0, 1, 0, p; }"
                     : "=r"(done) : "r"(a), "r"(ph) : "memory");
    }
}
__device__ __forceinline__ void fma2(ull& acc, ull a, ull b) {
    asm("fma.rn.f32x2 %0, %1, %2, %0;" : "+l"(acc) : "l"(a), "l"(b));
}
__device__ __forceinline__ ull dupf(float v) {
    ull r; asm("mov.b64 %0, {%1, %1};" : "=l"(r) : "f"(v)); return r;
}
__device__ __forceinline__ float rcp_(float x) {
    float y; asm("rcp.approx.f32 %0, %1;" : "=f"(y) : "f"(x)); return y;
}
__device__ __forceinline__ float sig_(float x)  { return rcp_(1.0f + __expf(-x)); }
__device__ __forceinline__ float tanh_(float x) { return fmaf(2.0f, rcp_(1.0f + __expf(-2.0f * x)), -1.0f); }

// 4 k-steps x 4 cols x 2 batches. LDS: 2 act (1 wf each, batches bp/bp+32) +
// 4 weight (64B broadcast line, 1 wf) = 6 wf per 16 FMA2.
__device__ __forceinline__ void dot4_2b(const float* __restrict__ a0p,
                                        const float* __restrict__ a1p,
                                        const float* __restrict__ wu,
                                        ull& x01, ull& x23, ull& y01, ull& y23) {
    float4 ha = *reinterpret_cast<const float4*>(a0p);
    float4 hb = *reinterpret_cast<const float4*>(a1p);
#pragma unroll
    for (int j = 0; j < 4; ++j) {
        ulonglong2 w = *reinterpret_cast<const ulonglong2*>(wu + j * 16);
        ull da = dupf((&ha.x)[j]);
        ull db = dupf((&hb.x)[j]);
        fma2(x01, da, w.x); fma2(x23, da, w.y);
        fma2(y01, db, w.x); fma2(y23, db, w.y);
    }
}

// ---------------- init: zero h, reset barrier counter ----------------
__global__ void k_init() {
    int i = blockIdx.x * blockDim.x + threadIdx.x;
    if (i < 4 * B_ * HCW) g_h[i] = 0.0f;
    if (i == 0) g_cnt = 0u;
}

// ---------------- x-projection GEMM (f32x2): g_xp = x @ W + bias ----------------
__global__ void __launch_bounds__(256, 2)
k_xproj(const float* __restrict__ x, const float* __restrict__ W,
        const float* __restrict__ bias) {
    __shared__ float As[16][132];
    __shared__ float Bs[16][128];
    const int tid = threadIdx.x;
    const int tx = tid & 15, ty = tid >> 4;
    const int m0 = blockIdx.x * 128;
    const int n0 = blockIdx.y * 128;

    ull acc2[8][4];
#pragma unroll
    for (int r = 0; r < 8; ++r)
#pragma unroll
        for (int c = 0; c < 4; ++c) acc2[r][c] = 0ull;

    for (int k0 = 0; k0 < I_; k0 += 16) {
        __syncthreads();
#pragma unroll
        for (int i = tid; i < 512; i += 256) {
            int r = i >> 2, g = i & 3;
            float4 v = *reinterpret_cast<const float4*>(
                x + (size_t)(m0 + r) * I_ + k0 + g * 4);
            As[g * 4 + 0][r] = v.x; As[g * 4 + 1][r] = v.y;
            As[g * 4 + 2][r] = v.z; As[g * 4 + 3][r] = v.w;
        }
#pragma unroll
        for (int i = tid; i < 512; i += 256) {
            int kk = i >> 5, g = i & 31;
            *reinterpret_cast<float4*>(&Bs[kk][g * 4]) =
                *reinterpret_cast<const float4*>(W + (size_t)(k0 + kk) * G4H + n0 + g * 4);
        }
        __syncthreads();
#pragma unroll
        for (int kk = 0; kk < 16; ++kk) {
            float a[8];
            *reinterpret_cast<float4*>(a)     = *reinterpret_cast<float4*>(&As[kk][ty * 8]);
            *reinterpret_cast<float4*>(a + 4) = *reinterpret_cast<float4*>(&As[kk][ty * 8 + 4]);
            ull bw[4];
            {
                ulonglong2 p0 = *reinterpret_cast<ulonglong2*>(&Bs[kk][tx * 4]);
                ulonglong2 p1 = *reinterpret_cast<ulonglong2*>(&Bs[kk][tx * 4 + 64]);
                bw[0] = p0.x; bw[1] = p0.y; bw[2] = p1.x; bw[3] = p1.y;
            }
#pragma unroll
            for (int r = 0; r < 8; ++r) {
                ull ha = dupf(a[r]);
#pragma unroll
                for (int c = 0; c < 4; ++c) fma2(acc2[r][c], ha, bw[c]);
            }
        }
    }

    const int b  = m0 >> 9;
    const int tb = (m0 & 511) + ty * 8;
    float4 bias0 = *reinterpret_cast<const float4*>(bias + n0 + tx * 4);
    float4 bias1 = *reinterpret_cast<const float4*>(bias + n0 + tx * 4 + 64);
#pragma unroll
    for (int r = 0; r < 8; ++r) {
        int t = tb + r;
#pragma unroll
        for (int grp = 0; grp < 2; ++grp) {
            int n  = n0 + tx * 4 + grp * 64;
            int q  = n >> 9;
            int cg = (n & 511) >> 2;
            float f0, f1, f2, f3;
            asm("mov.b64 {%0, %1}, %2;" : "=f"(f0), "=f"(f1) : "l"(acc2[r][grp * 2 + 0]));
            asm("mov.b64 {%0, %1}, %2;" : "=f"(f2), "=f"(f3) : "l"(acc2[r][grp * 2 + 1]));
            float4 v;
            v.x = f0 + (grp ? bias1.x : bias0.x);
            v.y = f1 + (grp ? bias1.y : bias0.y);
            v.z = f2 + (grp ? bias1.z : bias0.z);
            v.w = f3 + (grp ? bias1.w : bias0.w);
            *reinterpret_cast<float4*>(
                g_xp + (((size_t)t * GRID + cg) * B_ + b) * 16 + q * 4) = v;
        }
    }
}

// ---------------- persistent recurrent kernel (4-way K-split, 2-batch tiles) ----------------
__global__ void __launch_bounds__(NTH, 1)
k_lstm(const float* __restrict__ U, float* __restrict__ out) {
    extern __shared__ float sm[];
    float* sU   = sm;                 // [512][16]
    float* sH   = sU + F_U;           // 4 x [64][132]
    float* sXP  = sH + F_H;           // 4 x [64][16]
    float* sP   = sXP + F_XP;         // [4*64][20]
    float* sHo  = sP + F_P;           // [64][4]
    unsigned long long* mb = reinterpret_cast<unsigned long long*>(sHo + F_HO);
    const unsigned mbH0  = sm2u(mb);        // +8*c
    const unsigned mbXP0 = sm2u(mb + 4);    // +8*s
    const unsigned sH_u  = sm2u(sH);
    const unsigned sXP_u = sm2u(sXP);

    const int tid = threadIdx.x;
    const int blk = blockIdx.x;
    const int kh  = tid >> 7;         // K quarter 0..3
    const int r   = tid & 127;
    const int bp  = r >> 2;           // batch pair base: batches bp, bp+32
    const int cq  = r & 3;            // gate
    const int bu  = (tid & 255) >> 2; // update mapping (tid < 256)
    const int jl  = tid & 3;
    const int hcol = blk * 4 + jl;
    const int mychunk = blk >> 5;     // chunk this CTA's h columns land in
    const int c   = (blk + kh) & 3;   // chunk this quarter consumes
    float c_state = 0.0f;

    // ---- prologue ----
    if (tid == 0) {
#pragma unroll
        for (int i = 0; i < 8; ++i) mbar_init(mbH0 + i * 8, 1);
        asm volatile("fence.proxy.async.shared::cta;" ::: "memory");
    }
    for (int i = tid; i < 512 * 4; i += NTH) {
        int k = i >> 2, q = i & 3;
        float4 w = *reinterpret_cast<const float4*>(
            U + (size_t)k * G4H + q * H_ + blk * 4);
        *reinterpret_cast<float4*>(sU + k * 16 + q * 4) = w;
    }
    __syncthreads();
    if (tid == 384) {   // prefetch xp slots t=0..3
#pragma unroll
        for (int s = 0; s < 4; ++s) {
            mbar_arrive_expect(mbXP0 + s * 8, 4096);
            bulk_g2s(sXP_u + (unsigned)(s * 4096),
                     g_xp + ((size_t)s * GRID + blk) * (B_ * 16), 4096, mbXP0 + s * 8);
        }
    }

    const float* hb0_base = sH + c * (64 * HCW) + bp * HCW;
    const float* wb_base  = sU + (c * 128) * 16 + cq * 4;

    for (int t = 0; t < S_; ++t) {
        // ---- TMA issue: warps 0-3 lane0, one chunk each, consumption order ----
        if (tid < 128 && (tid & 31) == 0) {
            int w = tid >> 5;
            int cw = (blk + w) & 3;
            unsigned mbh = mbH0 + (unsigned)(cw * 8);
            mbar_arrive_expect(mbh, CHB);
            bulk_g2s(sH_u + (unsigned)(cw * CHB), g_h + cw * (64 * HCW), CHB, mbh);
        }

        // ---- accumulator init (quarter 0 carries x_proj) ----
        const int s = t & 3;
        ull x01, x23, y01, y23;
        if (kh == 0) {
            mbar_wait(mbXP0 + (unsigned)(s * 8), (unsigned)((t >> 2) & 1));
            float4 xa = *reinterpret_cast<const float4*>(
                sXP + s * (64 * 16) + bp * 16 + cq * 4);
            float4 xb = *reinterpret_cast<const float4*>(
                sXP + s * (64 * 16) + (bp + 32) * 16 + cq * 4);
            asm("mov.b64 %0, {%1, %2};" : "=l"(x01) : "f"(xa.x), "f"(xa.y));
            asm("mov.b64 %0, {%1, %2};" : "=l"(x23) : "f"(xa.z), "f"(xa.w));
            asm("mov.b64 %0, {%1, %2};" : "=l"(y01) : "f"(xb.x), "f"(xb.y));
            asm("mov.b64 %0, {%1, %2};" : "=l"(y23) : "f"(xb.z), "f"(xb.w));
        } else {
            x01 = x23 = y01 = y23 = 0ull;
        }

        // ---- this quarter's single 128-k chunk ----
        mbar_wait(mbH0 + (unsigned)(c * 8), (unsigned)(t & 1));
#pragma unroll 4
        for (int kk = 0; kk < 128; kk += 4)
            dot4_2b(hb0_base + kk, hb0_base + 32 * HCW + kk,
                    wb_base + kk * 16, x01, x23, y01, y23);

        // ---- write partials (2 batches) ----
        {
            float4 pv;
            asm("mov.b64 {%0, %1}, %2;" : "=f"(pv.x), "=f"(pv.y) : "l"(x01));
            asm("mov.b64 {%0, %1}, %2;" : "=f"(pv.z), "=f"(pv.w) : "l"(x23));
            *reinterpret_cast<float4*>(sP + (kh * 64 + bp) * 20 + cq * 4) = pv;
            asm("mov.b64 {%0, %1}, %2;" : "=f"(pv.x), "=f"(pv.y) : "l"(y01));
            asm("mov.b64 {%0, %1}, %2;" : "=f"(pv.z), "=f"(pv.w) : "l"(y23));
            *reinterpret_cast<float4*>(sP + (kh * 64 + bp + 32) * 20 + cq * 4) = pv;
        }
        __syncthreads();   // S1: partials ready, all chunk smem consumed

        if (tid == 384 && t + 4 < S_) {   // xp refill (slot s consumed)
            mbar_arrive_expect(mbXP0 + (unsigned)(s * 8), 4096);
            bulk_g2s(sXP_u + (unsigned)(s * 4096),
                     g_xp + ((size_t)(t + 4) * GRID + blk) * (B_ * 16), 4096,
                     mbXP0 + (unsigned)(s * 8));
        }

        // ---- cell update (first 256 threads): sum 4 quarter partials ----
        if (tid < 256) {
            float gi = 0.f, gf = 0.f, gg = 0.f, go = 0.f;
#pragma unroll
            for (int q = 0; q < 4; ++q) {
                const float* pq = sP + (q * 64 + bu) * 20 + jl;
                gi += pq[0]; gf += pq[4]; gg += pq[8]; go += pq[12];
            }
            float iv = sig_(gi);
            float fv = sig_(gf);
            float gt = tanh_(gg);
            float ov = sig_(go);
            c_state = fv * c_state + iv * gt;
            float hv = ov * tanh_(c_state);
            sHo[bu * 4 + jl] = hv;
            if (t == S_ - 1) {
                size_t base = (size_t)B_ * S_ * H_;
                out[base + (size_t)bu * H_ + hcol] = hv;
                out[base + (size_t)B_ * H_ + (size_t)bu * H_ + hcol] = c_state;
            }
        }
        __syncthreads();   // S2: sHo ready

        // ---- coalesced h/out writes ----
        if (tid < 64) {
            float4 hv4 = *reinterpret_cast<float4*>(sHo + tid * 4);
            *reinterpret_cast<float4*>(
                out + ((size_t)tid * S_ + t) * H_ + blk * 4) = hv4;
            *reinterpret_cast<float4*>(
                g_h + (size_t)(mychunk * 64 + tid) * HCW + (blk & 31) * 4) = hv4;
            __threadfence();
        }
        __syncthreads();   // S3: h stores fenced before barrier arrive

        // ---- grid barrier: REDG + monotonic acquire-poll ----
        if (tid == 0) {
            asm volatile("red.release.gpu.global.add.u32 [%0], %1;"
                         :: "l"(&g_cnt), "r"(1u) : "memory");
            unsigned target = (unsigned)(t + 1) * (unsigned)GRID;
            unsigned v;
            do {
                asm volatile("ld.acquire.gpu.global.u32 %0, [%1];"
                             : "=r"(v) : "l"(&g_cnt) : "memory");
            } while (v < target);
        }
        __syncthreads();
    }
}

// ---------------- launch ----------------
extern "C" void kernel_launch(void* const* d_in, const int* in_sizes, int n_in,
                              void* d_out, int out_size) {
    const float* x = nullptr; const float* W = nullptr;
    const float* U = nullptr; const float* bias = nullptr;
    for (int i = 0; i < n_in; ++i) {
        switch (in_sizes[i]) {
            case B_ * S_ * I_: x    = (const float*)d_in[i]; break;
            case I_ * G4H:     W    = (const float*)d_in[i]; break;
            case H_ * G4H:     U    = (const float*)d_in[i]; break;
            case G4H:          bias = (const float*)d_in[i]; break;
            default: break;
        }
    }
    if (!x && n_in > 0)    x    = (const float*)d_in[0];
    if (!W && n_in > 1)    W    = (const float*)d_in[1];
    if (!U && n_in > 2)    U    = (const float*)d_in[2];
    if (!bias && n_in > 3) bias = (const float*)d_in[3];

    cudaFuncSetAttribute(k_lstm, cudaFuncAttributeMaxDynamicSharedMemorySize,
                         SMEM_BYTES);
    k_init<<<(4 * B_ * HCW + 255) / 256, 256>>>();
    k_xproj<<<dim3((B_ * S_) / 128, G4H / 128), 256>>>(x, W, bias);
    k_lstm<<<GRID, NTH, SMEM_BYTES>>>(U, (float*)d_out);
}